// round 2
// baseline (speedup 1.0000x reference)
#include <cuda_runtime.h>
#include <math.h>

// ---------------- problem constants ----------------
constexpr int Bn = 4;
constexpr int Tn = 1024;
constexpr int En = 1024;
constexpr int Hn = 16;
constexpr int Dn = 64;
constexpr int Ln = 8;
constexpr int FFn = 4096;
constexpr int Vn = 50257;
constexpr int BT = Bn * Tn;           // 4096
constexpr float EPS = 1e-5f;
constexpr float SCALE = 0.03125f;     // E^-0.5 = 1/32

// ---------------- scratch (device globals; no allocations allowed) ----------------
__device__ float g_x  [BT * En];
__device__ float g_h  [BT * En];
__device__ float g_q  [BT * En];
__device__ float g_k  [BT * En];
__device__ float g_v  [BT * En];
__device__ float g_att[BT * En];
__device__ float g_ff [BT * FFn];
__device__ float g_wei[67108864];     // B*H*T*T = 4*16*1024*1024
__device__ float g_rownll[BT];

// ---------------- generic tiled GEMM ----------------
// C[m,n] = alpha * sum_k A[m,k] * B[k,n]  (+ bias[n]) (+ residual[m,n]) (relu)
// Batched via blockIdx.z: z -> (b = z/Hb, h = z%Hb); each pointer gets b*s?b + h*s?h.
// TRANSB: B element (k,n) is read from Bm[n*ldb + k].
template<int BM, int BN, int BK, int TM, int TN, bool TRANSB>
__global__ void gemm_kernel(
    int M, int N, int K,
    const float* __restrict__ A, int lda, long long sAb, long long sAh,
    const float* __restrict__ Bm, int ldb, long long sBb, long long sBh,
    float* __restrict__ C, int ldc, long long sCb, long long sCh,
    const float* __restrict__ bias,
    const float* __restrict__ residual,
    float alpha, int Hb, int relu)
{
    constexpr int THREADS = (BM / TM) * (BN / TN);
    __shared__ float As[BK][BM];
    __shared__ float Bs[BK][BN];

    int z = blockIdx.z;
    int zb = z / Hb, zh = z % Hb;
    A  += zb * sAb + zh * sAh;
    Bm += zb * sBb + zh * sBh;
    C  += zb * sCb + zh * sCh;
    if (residual) residual += zb * sCb + zh * sCh;

    const int tid = threadIdx.x;
    const int m0 = blockIdx.y * BM;
    const int n0 = blockIdx.x * BN;
    const int tr = tid / (BN / TN);
    const int tc = tid % (BN / TN);

    float acc[TM][TN];
#pragma unroll
    for (int i = 0; i < TM; i++)
#pragma unroll
        for (int j = 0; j < TN; j++) acc[i][j] = 0.f;

    for (int k0 = 0; k0 < K; k0 += BK) {
        // load A tile (BM x BK), stored transposed As[k][m]
#pragma unroll
        for (int e = tid; e < BM * BK; e += THREADS) {
            int row = e / BK, col = e % BK;
            int gm = m0 + row, gk = k0 + col;
            As[col][row] = (gm < M && gk < K) ? A[(long long)gm * lda + gk] : 0.f;
        }
        // load B tile (BK x BN)
#pragma unroll
        for (int e = tid; e < BK * BN; e += THREADS) {
            int row = e / BN, col = e % BN;
            int gk = k0 + row, gn = n0 + col;
            float val = 0.f;
            if (gk < K && gn < N)
                val = TRANSB ? Bm[(long long)gn * ldb + gk]
                             : Bm[(long long)gk * ldb + gn];
            Bs[row][col] = val;
        }
        __syncthreads();

#pragma unroll
        for (int k = 0; k < BK; k++) {
            float ra[TM], rb[TN];
#pragma unroll
            for (int i = 0; i < TM; i++) ra[i] = As[k][tr * TM + i];
#pragma unroll
            for (int j = 0; j < TN; j++) rb[j] = Bs[k][tc * TN + j];
#pragma unroll
            for (int i = 0; i < TM; i++)
#pragma unroll
                for (int j = 0; j < TN; j++)
                    acc[i][j] += ra[i] * rb[j];
        }
        __syncthreads();
    }

#pragma unroll
    for (int i = 0; i < TM; i++) {
        int gm = m0 + tr * TM + i;
        if (gm >= M) continue;
#pragma unroll
        for (int j = 0; j < TN; j++) {
            int gn = n0 + tc * TN + j;
            if (gn >= N) continue;
            float c = acc[i][j] * alpha;
            if (bias) c += bias[gn];
            if (residual) c += residual[(long long)gm * ldc + gn];
            if (relu) c = fmaxf(c, 0.f);
            C[(long long)gm * ldc + gn] = c;
        }
    }
}

// ---------------- embedding: x[b,t,:] = tok_emb[idx[b,t],:] + pos_emb[t,:] ----------------
__global__ void embed_kernel(const int* __restrict__ idx,
                             const float* __restrict__ tok,
                             const float* __restrict__ pos,
                             float* __restrict__ x)
{
    int bt = blockIdx.x;
    int t = bt % Tn;
    int token = idx[bt];
    const float* tr = tok + (long long)token * En;
    const float* pr = pos + (long long)t * En;
    float* xr = x + (long long)bt * En;
    for (int e = threadIdx.x; e < En; e += blockDim.x)
        xr[e] = tr[e] + pr[e];
}

// ---------------- layernorm over last dim (E=1024) ----------------
__global__ void ln_kernel(const float* __restrict__ x,
                          const float* __restrict__ g,
                          const float* __restrict__ b,
                          float* __restrict__ out)
{
    int row = blockIdx.x;
    const float* xr = x + (long long)row * En;
    float* orow = out + (long long)row * En;
    __shared__ float red[256];
    int tid = threadIdx.x;

    float s = 0.f;
    for (int e = tid; e < En; e += 256) s += xr[e];
    red[tid] = s; __syncthreads();
    for (int o = 128; o > 0; o >>= 1) { if (tid < o) red[tid] += red[tid + o]; __syncthreads(); }
    float mu = red[0] / (float)En;
    __syncthreads();

    float v = 0.f;
    for (int e = tid; e < En; e += 256) { float d = xr[e] - mu; v += d * d; }
    red[tid] = v; __syncthreads();
    for (int o = 128; o > 0; o >>= 1) { if (tid < o) red[tid] += red[tid + o]; __syncthreads(); }
    float rstd = rsqrtf(red[0] / (float)En + EPS);
    __syncthreads();

    for (int e = tid; e < En; e += 256)
        orow[e] = (xr[e] - mu) * rstd * g[e] + b[e];
}

// ---------------- causal softmax over wei rows; zeros upper triangle ----------------
__global__ void softmax_kernel(float* __restrict__ wei)
{
    int t = blockIdx.x;                       // row within [T,T] block
    long long base = ((long long)blockIdx.y * Tn + t) * (long long)Tn;
    float* row = wei + base;
    int len = t + 1;
    __shared__ float red[256];
    int tid = threadIdx.x;

    float m = -1e30f;
    for (int s = tid; s < len; s += 256) m = fmaxf(m, row[s]);
    red[tid] = m; __syncthreads();
    for (int o = 128; o > 0; o >>= 1) { if (tid < o) red[tid] = fmaxf(red[tid], red[tid + o]); __syncthreads(); }
    m = red[0]; __syncthreads();

    float sum = 0.f;
    for (int s = tid; s < len; s += 256) {
        float e = __expf(row[s] - m);
        row[s] = e;
        sum += e;
    }
    red[tid] = sum; __syncthreads();
    for (int o = 128; o > 0; o >>= 1) { if (tid < o) red[tid] += red[tid + o]; __syncthreads(); }
    float inv = 1.f / red[0];
    __syncthreads();

    for (int s = tid; s < len; s += 256) row[s] *= inv;
    for (int s = len + tid; s < Tn; s += 256) row[s] = 0.f;
}

// ---------------- per-row NLL over vocab ----------------
__global__ void nll_kernel(const float* __restrict__ logits,
                           const int* __restrict__ targets,
                           float* __restrict__ rownll)
{
    int row = blockIdx.x;
    const float* lr = logits + (long long)row * Vn;
    __shared__ float red[256];
    int tid = threadIdx.x;

    float m = -1e30f;
    for (int i = tid; i < Vn; i += 256) m = fmaxf(m, lr[i]);
    red[tid] = m; __syncthreads();
    for (int o = 128; o > 0; o >>= 1) { if (tid < o) red[tid] = fmaxf(red[tid], red[tid + o]); __syncthreads(); }
    m = red[0]; __syncthreads();

    float sum = 0.f;
    for (int i = tid; i < Vn; i += 256) sum += __expf(lr[i] - m);
    red[tid] = sum; __syncthreads();
    for (int o = 128; o > 0; o >>= 1) { if (tid < o) red[tid] += red[tid + o]; __syncthreads(); }

    if (tid == 0) {
        float lse = m + logf(red[0]);
        rownll[row] = -(lr[targets[row]] - lse);
    }
}

__global__ void mean_kernel(const float* __restrict__ rownll, float* __restrict__ out)
{
    __shared__ float red[256];
    int tid = threadIdx.x;
    float s = 0.f;
    for (int i = tid; i < BT; i += 256) s += rownll[i];
    red[tid] = s; __syncthreads();
    for (int o = 128; o > 0; o >>= 1) { if (tid < o) red[tid] += red[tid + o]; __syncthreads(); }
    if (tid == 0) out[0] = red[0] / (float)BT;
}

// ---------------- host launcher ----------------
extern "C" void kernel_launch(void* const* d_in, const int* in_sizes, int n_in,
                              void* d_out, int out_size)
{
    const int*   idx     = (const int*)  d_in[0];
    const int*   targets = (const int*)  d_in[1];
    const float* tok_emb = (const float*)d_in[2];
    const float* pos_emb = (const float*)d_in[3];
    const float* wq      = (const float*)d_in[4];
    const float* wk      = (const float*)d_in[5];
    const float* wv      = (const float*)d_in[6];
    const float* w_proj  = (const float*)d_in[7];
    const float* b_proj  = (const float*)d_in[8];
    const float* ln1_g   = (const float*)d_in[9];
    const float* ln1_b   = (const float*)d_in[10];
    const float* ln2_g   = (const float*)d_in[11];
    const float* ln2_b   = (const float*)d_in[12];
    const float* ff_w1   = (const float*)d_in[13];
    const float* ff_b1   = (const float*)d_in[14];
    const float* ff_w2   = (const float*)d_in[15];
    const float* ff_b2   = (const float*)d_in[16];
    const float* lnf_g   = (const float*)d_in[17];
    const float* lnf_b   = (const float*)d_in[18];
    const float* lm_w    = (const float*)d_in[19];
    const float* lm_b    = (const float*)d_in[20];
    float* out = (float*)d_out;

    float *x, *h, *q, *k, *v, *att, *ff, *wei, *rownll;
    cudaGetSymbolAddress((void**)&x,      g_x);
    cudaGetSymbolAddress((void**)&h,      g_h);
    cudaGetSymbolAddress((void**)&q,      g_q);
    cudaGetSymbolAddress((void**)&k,      g_k);
    cudaGetSymbolAddress((void**)&v,      g_v);
    cudaGetSymbolAddress((void**)&att,    g_att);
    cudaGetSymbolAddress((void**)&ff,     g_ff);
    cudaGetSymbolAddress((void**)&wei,    g_wei);
    cudaGetSymbolAddress((void**)&rownll, g_rownll);

    // x = tok_emb[idx] + pos_emb
    embed_kernel<<<BT, 256>>>(idx, tok_emb, pos_emb, x);

    const long long sTE = (long long)Tn * En;   // per-batch stride within [B,T,E]
    const long long sHTT = (long long)Hn * Tn * Tn;
    const long long sTT  = (long long)Tn * Tn;

    for (int l = 0; l < Ln; l++) {
        // h = LN1(x)
        ln_kernel<<<BT, 256>>>(x, ln1_g + (long long)l * En, ln1_b + (long long)l * En, h);

        // q/k/v: [BT,E] x per-head [E,D] -> stored as [B,T,H*D]
        dim3 gqkv(1, BT / 128, Hn);
        const float* wqs[3] = { wq + (long long)l * Hn * En * Dn,
                                wk + (long long)l * Hn * En * Dn,
                                wv + (long long)l * Hn * En * Dn };
        float* qs[3] = { q, k, v };
        for (int i = 0; i < 3; i++) {
            gemm_kernel<128, 64, 16, 8, 4, false><<<gqkv, 256>>>(
                BT, Dn, En,
                h, En, 0, 0,
                wqs[i], Dn, 0, (long long)En * Dn,
                qs[i], En, 0, Dn,
                nullptr, nullptr, 1.f, Hn, 0);
        }

        // wei = scale * q . k^T   (batched over b,h)
        dim3 gs(Tn / 128, Tn / 128, Bn * Hn);
        gemm_kernel<128, 128, 16, 8, 8, true><<<gs, 256>>>(
            Tn, Tn, Dn,
            q, En, sTE, Dn,
            k, En, sTE, Dn,
            wei, Tn, sHTT, sTT,
            nullptr, nullptr, SCALE, Hn, 0);

        // causal softmax rows
        softmax_kernel<<<dim3(Tn, Bn * Hn), 256>>>(wei);

        // att = wei . v
        dim3 ga(1, Tn / 128, Bn * Hn);
        gemm_kernel<128, 64, 16, 8, 4, false><<<ga, 256>>>(
            Tn, Dn, Tn,
            wei, Tn, sHTT, sTT,
            v, En, sTE, Dn,
            att, En, sTE, Dn,
            nullptr, nullptr, 1.f, Hn, 0);

        // x = x + att @ w_proj + b_proj
        dim3 gp(En / 128, BT / 128, 1);
        gemm_kernel<128, 128, 16, 8, 8, false><<<gp, 256>>>(
            BT, En, En,
            att, En, 0, 0,
            w_proj + (long long)l * En * En, En, 0, 0,
            x, En, 0, 0,
            b_proj + (long long)l * En, x, 1.f, 1, 0);

        // h = LN2(x)
        ln_kernel<<<BT, 256>>>(x, ln2_g + (long long)l * En, ln2_b + (long long)l * En, h);

        // ff = relu(h @ ff_w1 + ff_b1)
        dim3 gf1(FFn / 128, BT / 128, 1);
        gemm_kernel<128, 128, 16, 8, 8, false><<<gf1, 256>>>(
            BT, FFn, En,
            h, En, 0, 0,
            ff_w1 + (long long)l * En * FFn, FFn, 0, 0,
            ff, FFn, 0, 0,
            ff_b1 + (long long)l * FFn, nullptr, 1.f, 1, 1);

        // x = x + ff @ ff_w2 + ff_b2
        dim3 gf2(En / 128, BT / 128, 1);
        gemm_kernel<128, 128, 16, 8, 8, false><<<gf2, 256>>>(
            BT, En, FFn,
            ff, FFn, 0, 0,
            ff_w2 + (long long)l * FFn * En, En, 0, 0,
            x, En, 0, 0,
            ff_b2 + (long long)l * En, x, 1.f, 1, 0);
    }

    // h = LN_f(x)
    ln_kernel<<<BT, 256>>>(x, lnf_g, lnf_b, h);

    // logits = h @ lm_w + lm_b  -> d_out
    dim3 gl((Vn + 127) / 128, BT / 128, 1);
    gemm_kernel<128, 128, 16, 8, 8, false><<<gl, 256>>>(
        BT, Vn, En,
        h, En, 0, 0,
        lm_w, Vn, 0, 0,
        out, Vn, 0, 0,
        lm_b, nullptr, 1.f, 1, 0);

    // loss (if the output buffer includes it)
    if ((long long)out_size > (long long)BT * Vn) {
        nll_kernel<<<BT, 256>>>(out, targets, rownll);
        mean_kernel<<<1, 256>>>(rownll, out + (long long)BT * Vn);
    }
}

// round 5
// speedup vs baseline: 6.5988x; 6.5988x over previous
#include <cuda_runtime.h>
#include <math.h>
#include <stdint.h>

// ---------------- problem constants ----------------
constexpr int Bn = 4;
constexpr int Tn = 1024;
constexpr int En = 1024;
constexpr int Hn = 16;
constexpr int Dn = 64;
constexpr int Ln = 8;
constexpr int FFn = 4096;
constexpr int Vn = 50257;
constexpr int VPAD = 50304;           // Vn padded to multiple of 128
constexpr int BT = Bn * Tn;           // 4096
constexpr float EPS = 1e-5f;
constexpr float SCALE = 0.03125f;     // E^-0.5 = 1/32

// ---------------- scratch (device globals; no allocations allowed) ----------------
__device__ float g_x  [BT * En];
__device__ float g_h  [BT * En];
__device__ float g_q  [BT * En];
__device__ float g_k  [BT * En];
__device__ float g_v  [BT * En];
__device__ float g_att[BT * En];
__device__ float g_ff [BT * FFn];
__device__ float g_wei[67108864];     // B*H*T*T
__device__ float g_wpad[En * VPAD];   // padded lm_w
__device__ float g_rownll[BT];

// ---------------- PTX helpers ----------------
__device__ __forceinline__ void cp16(uint32_t dst, const void* src) {
    asm volatile("cp.async.cg.shared.global [%0], [%1], 16;\n" :: "r"(dst), "l"(src));
}
__device__ __forceinline__ void cp_commit() {
    asm volatile("cp.async.commit_group;\n" ::);
}
template<int N> __device__ __forceinline__ void cp_wait() {
    asm volatile("cp.async.wait_group %0;\n" :: "n"(N));
}
__device__ __forceinline__ uint32_t ld_tf32(const float* p) {
    uint32_t u;
    asm("cvt.rna.tf32.f32 %0, %1;" : "=r"(u) : "f"(*p));
    return u;
}
__device__ __forceinline__ void mma8(float* c, const uint32_t* a, const uint32_t* b) {
    asm volatile(
        "mma.sync.aligned.m16n8k8.row.col.f32.tf32.tf32.f32 "
        "{%0,%1,%2,%3}, {%4,%5,%6,%7}, {%8,%9}, {%0,%1,%2,%3};\n"
        : "+f"(c[0]), "+f"(c[1]), "+f"(c[2]), "+f"(c[3])
        : "r"(a[0]), "r"(a[1]), "r"(a[2]), "r"(a[3]), "r"(b[0]), "r"(b[1]));
}

// ---------------- tf32 tensor-core GEMM ----------------
// C[m,n] = alpha * sum_k A[m,k]*B[k,n] (+bias[n]) (+residual) (relu)
// Batched via blockIdx.z -> (zb = z/Hb, zh = z%Hb) with per-operand strides.
// TRANSB: B element (k,n) read from Bm[n*ldb + k].
// Requires: M % BM == 0, K % BK == 0, and for B loads/stores handled below:
//   non-TRANSB B tile loads are unguarded (caller guarantees padded N),
//   C stores + bias guarded by n < N.
template<int BM, int BN, int WM, int WN, int BK, bool TRANSB>
__global__ void __launch_bounds__(256)
gemm_tf32(int M, int N, int K,
          const float* __restrict__ A, int lda, long long sAb, long long sAh,
          const float* __restrict__ Bm, int ldb, long long sBb, long long sBh,
          float* __restrict__ C, int ldc, long long sCb, long long sCh,
          const float* __restrict__ bias, const float* __restrict__ residual,
          float alpha, int Hb, int relu)
{
    extern __shared__ float smem[];
    constexpr int ASTR   = BK + 4;
    constexpr int BSTR   = TRANSB ? (BK + 4) : (BN + 8);
    constexpr int A_TILE = BM * ASTR;
    constexpr int B_TILE = TRANSB ? BN * BSTR : BK * BSTR;
    constexpr int MT = WM / 16, NT = WN / 8;
    constexpr int KV = BK / 4;

    float* As = smem;
    float* Bs = smem + 2 * A_TILE;

    const int z = blockIdx.z;
    const int zb = z / Hb, zh = z % Hb;
    A  += zb * sAb + zh * sAh;
    Bm += zb * sBb + zh * sBh;
    C  += zb * sCb + zh * sCh;
    const float* Res = residual ? residual + zb * sCb + zh * sCh : nullptr;

    const int tid  = threadIdx.x;
    const int lane = tid & 31, wid = tid >> 5;
    const int m0 = blockIdx.x * BM, n0 = blockIdx.y * BN;
    constexpr int WNC = BN / WN;
    const int wm = wid / WNC, wn = wid % WNC;
    const int qr = lane >> 2, qc = lane & 3;

    float acc[MT][NT][4];
#pragma unroll
    for (int i = 0; i < MT; i++)
#pragma unroll
        for (int j = 0; j < NT; j++)
#pragma unroll
            for (int r = 0; r < 4; r++) acc[i][j][r] = 0.f;

    const uint32_t sA = (uint32_t)__cvta_generic_to_shared(As);
    const uint32_t sB = (uint32_t)__cvta_generic_to_shared(Bs);

    auto load_A = [&](int s, int k0) {
#pragma unroll
        for (int i = 0; i < (BM * KV) / 256; i++) {
            int e   = tid + i * 256;
            int row = e / KV;
            int kc  = (e % KV) * 4;
            const float* src = A + (long long)(m0 + row) * lda + k0 + kc;
            cp16(sA + (uint32_t)(s * A_TILE + row * ASTR + kc) * 4u, src);
        }
    };
    auto load_B = [&](int s, int k0) {
        if (TRANSB) {
#pragma unroll
            for (int i = 0; i < (BN * KV) / 256; i++) {
                int e  = tid + i * 256;
                int n  = e / KV;
                int kc = (e % KV) * 4;
                const float* src = Bm + (long long)(n0 + n) * ldb + k0 + kc;
                cp16(sB + (uint32_t)(s * B_TILE + n * BSTR + kc) * 4u, src);
            }
        } else {
#pragma unroll
            for (int i = 0; i < (BK * (BN / 4)) / 256; i++) {
                int e  = tid + i * 256;
                int k  = e / (BN / 4);
                int nc = (e % (BN / 4)) * 4;
                const float* src = Bm + (long long)(k0 + k) * ldb + n0 + nc;
                cp16(sB + (uint32_t)(s * B_TILE + k * BSTR + nc) * 4u, src);
            }
        }
    };

    const int iters = K / BK;
    load_A(0, 0); load_B(0, 0);
    cp_commit();

    for (int it = 0; it < iters; it++) {
        const int s = it & 1;
        if (it + 1 < iters) {
            load_A(s ^ 1, (it + 1) * BK);
            load_B(s ^ 1, (it + 1) * BK);
            cp_commit();
            cp_wait<1>();
        } else {
            cp_wait<0>();
        }
        __syncthreads();

        const float* Ab = As + s * A_TILE;
        const float* Bb = Bs + s * B_TILE;
#pragma unroll
        for (int ks = 0; ks < BK; ks += 8) {
            uint32_t af[MT][4], bf[NT][2];
#pragma unroll
            for (int mt = 0; mt < MT; mt++) {
                int r0 = wm * WM + mt * 16 + qr;
                af[mt][0] = ld_tf32(Ab + r0 * ASTR + ks + qc);
                af[mt][1] = ld_tf32(Ab + (r0 + 8) * ASTR + ks + qc);
                af[mt][2] = ld_tf32(Ab + r0 * ASTR + ks + qc + 4);
                af[mt][3] = ld_tf32(Ab + (r0 + 8) * ASTR + ks + qc + 4);
            }
#pragma unroll
            for (int nt = 0; nt < NT; nt++) {
                int cn = wn * WN + nt * 8 + qr;
                if (TRANSB) {
                    bf[nt][0] = ld_tf32(Bb + cn * BSTR + ks + qc);
                    bf[nt][1] = ld_tf32(Bb + cn * BSTR + ks + qc + 4);
                } else {
                    bf[nt][0] = ld_tf32(Bb + (ks + qc) * BSTR + cn);
                    bf[nt][1] = ld_tf32(Bb + (ks + qc + 4) * BSTR + cn);
                }
            }
#pragma unroll
            for (int mt = 0; mt < MT; mt++)
#pragma unroll
                for (int nt = 0; nt < NT; nt++)
                    mma8(acc[mt][nt], af[mt], bf[nt]);
        }
        __syncthreads();
    }

    // epilogue
#pragma unroll
    for (int mt = 0; mt < MT; mt++) {
#pragma unroll
        for (int nt = 0; nt < NT; nt++) {
            int r = m0 + wm * WM + mt * 16 + qr;
            int c = n0 + wn * WN + nt * 8 + 2 * qc;
#pragma unroll
            for (int v = 0; v < 4; v++) {
                int rr = r + (v >> 1) * 8;
                int cc = c + (v & 1);
                if (cc >= N) continue;
                float val = acc[mt][nt][v] * alpha;
                if (bias) val += bias[cc];
                long long off = (long long)rr * ldc + cc;
                if (Res) val += Res[off];
                if (relu) val = fmaxf(val, 0.f);
                C[off] = val;
            }
        }
    }
}

// ---------------- elementwise kernels ----------------
__global__ void embed_kernel(const int* __restrict__ idx,
                             const float* __restrict__ tok,
                             const float* __restrict__ pos,
                             float* __restrict__ x)
{
    int bt = blockIdx.x;
    int t = bt % Tn;
    int token = idx[bt];
    const float* tr = tok + (long long)token * En;
    const float* pr = pos + (long long)t * En;
    float* xr = x + (long long)bt * En;
    for (int e = threadIdx.x; e < En; e += blockDim.x)
        xr[e] = tr[e] + pr[e];
}

__global__ void pad_lm_w(const float* __restrict__ src, float* __restrict__ dst)
{
    int r = blockIdx.x;
    const float* s = src + (long long)r * Vn;
    float* d = dst + (long long)r * VPAD;
    for (int c = threadIdx.x; c < VPAD; c += blockDim.x)
        d[c] = (c < Vn) ? s[c] : 0.f;
}

__global__ void ln_kernel(const float* __restrict__ x,
                          const float* __restrict__ g,
                          const float* __restrict__ b,
                          float* __restrict__ out)
{
    int row = blockIdx.x;
    const float* xr = x + (long long)row * En;
    float* orow = out + (long long)row * En;
    __shared__ float red[256];
    int tid = threadIdx.x;

    float s = 0.f;
    for (int e = tid; e < En; e += 256) s += xr[e];
    red[tid] = s; __syncthreads();
    for (int o = 128; o > 0; o >>= 1) { if (tid < o) red[tid] += red[tid + o]; __syncthreads(); }
    float mu = red[0] / (float)En;
    __syncthreads();

    float v = 0.f;
    for (int e = tid; e < En; e += 256) { float d = xr[e] - mu; v += d * d; }
    red[tid] = v; __syncthreads();
    for (int o = 128; o > 0; o >>= 1) { if (tid < o) red[tid] += red[tid + o]; __syncthreads(); }
    float rstd = rsqrtf(red[0] / (float)En + EPS);
    __syncthreads();

    for (int e = tid; e < En; e += 256)
        orow[e] = (xr[e] - mu) * rstd * g[e] + b[e];
}

__global__ void softmax_kernel(float* __restrict__ wei)
{
    int t = blockIdx.x;
    long long base = ((long long)blockIdx.y * Tn + t) * (long long)Tn;
    float* row = wei + base;
    int len = t + 1;
    __shared__ float red[256];
    int tid = threadIdx.x;

    float m = -1e30f;
    for (int s = tid; s < len; s += 256) m = fmaxf(m, row[s]);
    red[tid] = m; __syncthreads();
    for (int o = 128; o > 0; o >>= 1) { if (tid < o) red[tid] = fmaxf(red[tid], red[tid + o]); __syncthreads(); }
    m = red[0]; __syncthreads();

    float sum = 0.f;
    for (int s = tid; s < len; s += 256) {
        float e = __expf(row[s] - m);
        row[s] = e;
        sum += e;
    }
    red[tid] = sum; __syncthreads();
    for (int o = 128; o > 0; o >>= 1) { if (tid < o) red[tid] += red[tid + o]; __syncthreads(); }
    float inv = 1.f / red[0];
    __syncthreads();

    for (int s = tid; s < len; s += 256) row[s] *= inv;
    for (int s = len + tid; s < Tn; s += 256) row[s] = 0.f;
}

__global__ void nll_kernel(const float* __restrict__ logits,
                           const int* __restrict__ targets,
                           float* __restrict__ rownll)
{
    int row = blockIdx.x;
    const float* lr = logits + (long long)row * Vn;
    __shared__ float red[256];
    int tid = threadIdx.x;

    float m = -1e30f;
    for (int i = tid; i < Vn; i += 256) m = fmaxf(m, lr[i]);
    red[tid] = m; __syncthreads();
    for (int o = 128; o > 0; o >>= 1) { if (tid < o) red[tid] = fmaxf(red[tid], red[tid + o]); __syncthreads(); }
    m = red[0]; __syncthreads();

    float sum = 0.f;
    for (int i = tid; i < Vn; i += 256) sum += __expf(lr[i] - m);
    red[tid] = sum; __syncthreads();
    for (int o = 128; o > 0; o >>= 1) { if (tid < o) red[tid] += red[tid + o]; __syncthreads(); }

    if (tid == 0) {
        float lse = m + logf(red[0]);
        rownll[row] = -(lr[targets[row]] - lse);
    }
}

__global__ void mean_kernel(const float* __restrict__ rownll, float* __restrict__ out)
{
    __shared__ float red[256];
    int tid = threadIdx.x;
    float s = 0.f;
    for (int i = tid; i < BT; i += 256) s += rownll[i];
    red[tid] = s; __syncthreads();
    for (int o = 128; o > 0; o >>= 1) { if (tid < o) red[tid] += red[tid + o]; __syncthreads(); }
    if (tid == 0) out[0] = red[0] / (float)BT;
}

// ---------------- host launcher ----------------
// Config A: BM=128 BN=128 WM=64 WN=32 BK=32  (generic big GEMMs)
// Config B: BM=128 BN=64  WM=32 WN=32 BK=32  (N=64 GEMMs)
static constexpr int SMEM_A  = 2 * (128 * 36 + 32 * 136) * 4;   // 71680
static constexpr int SMEM_AT = 2 * (128 * 36 + 128 * 36) * 4;   // 73728
static constexpr int SMEM_B  = 2 * (128 * 36 + 32 * 72) * 4;    // 55296

extern "C" void kernel_launch(void* const* d_in, const int* in_sizes, int n_in,
                              void* d_out, int out_size)
{
    const int*   idx     = (const int*)  d_in[0];
    const int*   targets = (const int*)  d_in[1];
    const float* tok_emb = (const float*)d_in[2];
    const float* pos_emb = (const float*)d_in[3];
    const float* wq      = (const float*)d_in[4];
    const float* wk      = (const float*)d_in[5];
    const float* wv      = (const float*)d_in[6];
    const float* w_proj  = (const float*)d_in[7];
    const float* b_proj  = (const float*)d_in[8];
    const float* ln1_g   = (const float*)d_in[9];
    const float* ln1_b   = (const float*)d_in[10];
    const float* ln2_g   = (const float*)d_in[11];
    const float* ln2_b   = (const float*)d_in[12];
    const float* ff_w1   = (const float*)d_in[13];
    const float* ff_b1   = (const float*)d_in[14];
    const float* ff_w2   = (const float*)d_in[15];
    const float* ff_b2   = (const float*)d_in[16];
    const float* lnf_g   = (const float*)d_in[17];
    const float* lnf_b   = (const float*)d_in[18];
    const float* lm_w    = (const float*)d_in[19];
    const float* lm_b    = (const float*)d_in[20];
    float* out = (float*)d_out;

    float *x, *h, *q, *k, *v, *att, *ff, *wei, *wpad, *rownll;
    cudaGetSymbolAddress((void**)&x,      g_x);
    cudaGetSymbolAddress((void**)&h,      g_h);
    cudaGetSymbolAddress((void**)&q,      g_q);
    cudaGetSymbolAddress((void**)&k,      g_k);
    cudaGetSymbolAddress((void**)&v,      g_v);
    cudaGetSymbolAddress((void**)&att,    g_att);
    cudaGetSymbolAddress((void**)&ff,     g_ff);
    cudaGetSymbolAddress((void**)&wei,    g_wei);
    cudaGetSymbolAddress((void**)&wpad,   g_wpad);
    cudaGetSymbolAddress((void**)&rownll, g_rownll);

    auto kA  = gemm_tf32<128, 128, 64, 32, 32, false>;
    auto kAT = gemm_tf32<128, 128, 64, 32, 32, true>;
    auto kB  = gemm_tf32<128, 64, 32, 32, 32, false>;
    cudaFuncSetAttribute(kA,  cudaFuncAttributeMaxDynamicSharedMemorySize, SMEM_A);
    cudaFuncSetAttribute(kAT, cudaFuncAttributeMaxDynamicSharedMemorySize, SMEM_AT);
    cudaFuncSetAttribute(kB,  cudaFuncAttributeMaxDynamicSharedMemorySize, SMEM_B);

    // x = tok_emb[idx] + pos_emb ; pad lm_w
    embed_kernel<<<BT, 256>>>(idx, tok_emb, pos_emb, x);
    pad_lm_w<<<En, 256>>>(lm_w, wpad);

    const long long sTE  = (long long)Tn * En;
    const long long sHTT = (long long)Hn * Tn * Tn;
    const long long sTT  = (long long)Tn * Tn;

    for (int l = 0; l < Ln; l++) {
        // h = LN1(x)
        ln_kernel<<<BT, 256>>>(x, ln1_g + (long long)l * En, ln1_b + (long long)l * En, h);

        // q/k/v = h @ W[head]  (batched over heads, N=64)
        const float* wqs[3] = { wq + (long long)l * Hn * En * Dn,
                                wk + (long long)l * Hn * En * Dn,
                                wv + (long long)l * Hn * En * Dn };
        float* qs[3] = { q, k, v };
        for (int i = 0; i < 3; i++) {
            kB<<<dim3(BT / 128, 1, Hn), 256, SMEM_B>>>(
                BT, Dn, En,
                h, En, 0, 0,
                wqs[i], Dn, 0, (long long)En * Dn,
                qs[i], En, 0, Dn,
                nullptr, nullptr, 1.f, Hn, 0);
        }

        // wei = scale * q . k^T (batched over b,h)
        kAT<<<dim3(Tn / 128, Tn / 128, Bn * Hn), 256, SMEM_AT>>>(
            Tn, Tn, Dn,
            q, En, sTE, Dn,
            k, En, sTE, Dn,
            wei, Tn, sHTT, sTT,
            nullptr, nullptr, SCALE, Hn, 0);

        // causal softmax
        softmax_kernel<<<dim3(Tn, Bn * Hn), 256>>>(wei);

        // att = wei . v
        kB<<<dim3(Tn / 128, 1, Bn * Hn), 256, SMEM_B>>>(
            Tn, Dn, Tn,
            wei, Tn, sHTT, sTT,
            v, En, sTE, Dn,
            att, En, sTE, Dn,
            nullptr, nullptr, 1.f, Hn, 0);

        // x = x + att @ w_proj + b_proj
        kA<<<dim3(BT / 128, En / 128, 1), 256, SMEM_A>>>(
            BT, En, En,
            att, En, 0, 0,
            w_proj + (long long)l * En * En, En, 0, 0,
            x, En, 0, 0,
            b_proj + (long long)l * En, x, 1.f, 1, 0);

        // h = LN2(x)
        ln_kernel<<<BT, 256>>>(x, ln2_g + (long long)l * En, ln2_b + (long long)l * En, h);

        // ff = relu(h @ ff_w1 + ff_b1)
        kA<<<dim3(BT / 128, FFn / 128, 1), 256, SMEM_A>>>(
            BT, FFn, En,
            h, En, 0, 0,
            ff_w1 + (long long)l * En * FFn, FFn, 0, 0,
            ff, FFn, 0, 0,
            ff_b1 + (long long)l * FFn, nullptr, 1.f, 1, 1);

        // x = x + ff @ ff_w2 + ff_b2
        kA<<<dim3(BT / 128, En / 128, 1), 256, SMEM_A>>>(
            BT, En, FFn,
            ff, FFn, 0, 0,
            ff_w2 + (long long)l * FFn * En, En, 0, 0,
            x, En, 0, 0,
            ff_b2 + (long long)l * En, x, 1.f, 1, 0);
    }

    // h = LN_f(x)
    ln_kernel<<<BT, 256>>>(x, lnf_g, lnf_b, h);

    // logits = h @ lm_w + lm_b (lm_w padded to VPAD for aligned loads)
    kA<<<dim3(BT / 128, VPAD / 128, 1), 256, SMEM_A>>>(
        BT, Vn, En,
        h, En, 0, 0,
        wpad, VPAD, 0, 0,
        out, Vn, 0, 0,
        lm_b, nullptr, 1.f, 1, 0);

    // loss
    if ((long long)out_size > (long long)BT * Vn) {
        nll_kernel<<<BT, 256>>>(out, targets, rownll);
        mean_kernel<<<1, 256>>>(rownll, out + (long long)BT * Vn);
    }
}

// round 6
// speedup vs baseline: 9.0576x; 1.3726x over previous
#include <cuda_runtime.h>
#include <math.h>
#include <stdint.h>

// ---------------- problem constants ----------------
constexpr int Bn = 4;
constexpr int Tn = 1024;
constexpr int En = 1024;
constexpr int Hn = 16;
constexpr int Dn = 64;
constexpr int Ln = 8;
constexpr int FFn = 4096;
constexpr int Vn = 50257;
constexpr int VPAD = 50304;
constexpr int BT = Bn * Tn;
constexpr float EPS = 1e-5f;
constexpr float SCALE = 0.03125f;     // E^-0.5

// ---------------- scratch (device globals) ----------------
__device__ float g_x   [BT * En];
__device__ float g_h   [BT * En];
__device__ float g_qkv [BT * 3 * En];          // [BT][3072]: q | k | v (head-concat)
__device__ float g_att [BT * En];
__device__ float g_ff  [BT * FFn];
__device__ float g_wqkv[Ln * En * 3 * En];     // [L][E][3*H*D] rounded
__device__ float g_wprj[Ln * En * En];         // rounded copy of w_proj
__device__ float g_wff1[Ln * En * FFn];        // rounded
__device__ float g_wff2[Ln * FFn * En];        // rounded
__device__ float g_wpad[En * VPAD];            // padded + rounded lm_w
__device__ float g_rownll[BT];

// ---------------- PTX helpers ----------------
__device__ __forceinline__ void cp16(uint32_t dst, const void* src) {
    asm volatile("cp.async.cg.shared.global [%0], [%1], 16;\n" :: "r"(dst), "l"(src));
}
__device__ __forceinline__ void cp_commit() { asm volatile("cp.async.commit_group;\n" ::); }
template<int N> __device__ __forceinline__ void cp_wait() {
    asm volatile("cp.async.wait_group %0;\n" :: "n"(N));
}
__device__ __forceinline__ float rnd_tf32(float x) {
    uint32_t u;
    asm("cvt.rna.tf32.f32 %0, %1;" : "=r"(u) : "f"(x));
    return __uint_as_float(u);
}
__device__ __forceinline__ void mma8(float* c, const uint32_t* a, const uint32_t* b) {
    asm volatile(
        "mma.sync.aligned.m16n8k8.row.col.f32.tf32.tf32.f32 "
        "{%0,%1,%2,%3}, {%4,%5,%6,%7}, {%8,%9}, {%0,%1,%2,%3};\n"
        : "+f"(c[0]), "+f"(c[1]), "+f"(c[2]), "+f"(c[3])
        : "r"(a[0]), "r"(a[1]), "r"(a[2]), "r"(a[3]), "r"(b[0]), "r"(b[1]));
}

// ---------------- tf32 GEMM (inputs pre-rounded to tf32; no cvt in loop) ----------------
// flags: bit0 = relu, bit1 = round output to tf32
template<int BM, int BN, int WM, int WN, int BK>
__global__ void __launch_bounds__(256)
gemm_tf32(int M, int N, int K,
          const float* __restrict__ A, int lda,
          const float* __restrict__ Bm, int ldb,
          float* __restrict__ C, int ldc,
          const float* __restrict__ bias, const float* __restrict__ residual,
          int flags)
{
    extern __shared__ float smem[];
    constexpr int ASTR   = BK + 4;
    constexpr int BSTR   = BN + 8;
    constexpr int A_TILE = BM * ASTR;
    constexpr int B_TILE = BK * BSTR;
    constexpr int MT = WM / 16, NT = WN / 8;
    constexpr int KV = BK / 4;

    float* As = smem;
    float* Bs = smem + 2 * A_TILE;

    const int tid  = threadIdx.x;
    const int lane = tid & 31, wid = tid >> 5;
    const int m0 = blockIdx.x * BM, n0 = blockIdx.y * BN;
    constexpr int WNC = BN / WN;
    const int wm = wid / WNC, wn = wid % WNC;
    const int qr = lane >> 2, qc = lane & 3;

    float acc[MT][NT][4];
#pragma unroll
    for (int i = 0; i < MT; i++)
#pragma unroll
        for (int j = 0; j < NT; j++)
#pragma unroll
            for (int r = 0; r < 4; r++) acc[i][j][r] = 0.f;

    const uint32_t sA = (uint32_t)__cvta_generic_to_shared(As);
    const uint32_t sB = (uint32_t)__cvta_generic_to_shared(Bs);

    auto load_A = [&](int s, int k0) {
#pragma unroll
        for (int i = 0; i < (BM * KV) / 256; i++) {
            int e   = tid + i * 256;
            int row = e / KV;
            int kc  = (e % KV) * 4;
            cp16(sA + (uint32_t)(s * A_TILE + row * ASTR + kc) * 4u,
                 A + (long long)(m0 + row) * lda + k0 + kc);
        }
    };
    auto load_B = [&](int s, int k0) {
#pragma unroll
        for (int i = 0; i < (BK * (BN / 4)) / 256; i++) {
            int e  = tid + i * 256;
            int k  = e / (BN / 4);
            int nc = (e % (BN / 4)) * 4;
            cp16(sB + (uint32_t)(s * B_TILE + k * BSTR + nc) * 4u,
                 Bm + (long long)(k0 + k) * ldb + n0 + nc);
        }
    };

    const int iters = K / BK;
    load_A(0, 0); load_B(0, 0);
    cp_commit();

    for (int it = 0; it < iters; it++) {
        const int s = it & 1;
        if (it + 1 < iters) {
            load_A(s ^ 1, (it + 1) * BK);
            load_B(s ^ 1, (it + 1) * BK);
            cp_commit();
            cp_wait<1>();
        } else {
            cp_wait<0>();
        }
        __syncthreads();

        const float* Ab = As + s * A_TILE;
        const float* Bb = Bs + s * B_TILE;
#pragma unroll
        for (int ks = 0; ks < BK; ks += 8) {
            uint32_t af[MT][4], bf[NT][2];
#pragma unroll
            for (int mt = 0; mt < MT; mt++) {
                int r0 = wm * WM + mt * 16 + qr;
                af[mt][0] = __float_as_uint(Ab[r0 * ASTR + ks + qc]);
                af[mt][1] = __float_as_uint(Ab[(r0 + 8) * ASTR + ks + qc]);
                af[mt][2] = __float_as_uint(Ab[r0 * ASTR + ks + qc + 4]);
                af[mt][3] = __float_as_uint(Ab[(r0 + 8) * ASTR + ks + qc + 4]);
            }
#pragma unroll
            for (int nt = 0; nt < NT; nt++) {
                int cn = wn * WN + nt * 8 + qr;
                bf[nt][0] = __float_as_uint(Bb[(ks + qc) * BSTR + cn]);
                bf[nt][1] = __float_as_uint(Bb[(ks + qc + 4) * BSTR + cn]);
            }
#pragma unroll
            for (int mt = 0; mt < MT; mt++)
#pragma unroll
                for (int nt = 0; nt < NT; nt++)
                    mma8(acc[mt][nt], af[mt], bf[nt]);
        }
        __syncthreads();
    }

    const int relu = flags & 1, roundo = flags & 2;
#pragma unroll
    for (int mt = 0; mt < MT; mt++) {
#pragma unroll
        for (int nt = 0; nt < NT; nt++) {
            int r = m0 + wm * WM + mt * 16 + qr;
            int c = n0 + wn * WN + nt * 8 + 2 * qc;
#pragma unroll
            for (int v = 0; v < 4; v++) {
                int rr = r + (v >> 1) * 8;
                int cc = c + (v & 1);
                if (cc >= N) continue;
                float val = acc[mt][nt][v];
                if (bias) val += bias[cc];
                long long off = (long long)rr * ldc + cc;
                if (residual) val += residual[off];
                if (relu) val = fmaxf(val, 0.f);
                if (roundo) val = rnd_tf32(val);
                C[off] = val;
            }
        }
    }
}

// ---------------- fused causal flash attention (tf32 mma) ----------------
// grid: (8 row-blocks, 64 b*h), 256 threads = 8 warps x 16 rows.
// qkv: [BT][3072] pre-rounded tf32. att out: [BT][1024] rounded tf32.
constexpr int FBR = 128, FBC = 64;
constexpr int QSTR = 68, KSTR = 68, VSTR = 72, PSTR = 68;
constexpr int FLASH_SMEM = (FBR * QSTR + FBC * KSTR + FBC * VSTR) * 4;  // 70656

__global__ void __launch_bounds__(256)
flash_kernel(const float* __restrict__ qkv, float* __restrict__ att)
{
    extern __shared__ float sm[];
    float* Ps = sm;                         // Q staging, then P
    float* Ks = sm + FBR * QSTR;
    float* Vs = Ks + FBC * KSTR;

    const int ib = 7 - blockIdx.x;          // heavy blocks first
    const int bh = blockIdx.y;
    const int b = bh >> 4, h = bh & 15;
    const int tid = threadIdx.x, lane = tid & 31, w = tid >> 5;
    const int qr = lane >> 2, qc = lane & 3;

    const float* qbase = qkv + (long long)b * Tn * 3072 + h * 64;
    const float* kbase = qbase + 1024;
    const float* vbase = qbase + 2048;

    // stage Q tile [128 x 64]
    {
        uint32_t sQ = (uint32_t)__cvta_generic_to_shared(Ps);
        for (int e = tid; e < FBR * 16; e += 256) {
            int r = e >> 4, c4 = (e & 15) << 2;
            cp16(sQ + (uint32_t)(r * QSTR + c4) * 4u,
                 qbase + (long long)(ib * FBR + r) * 3072 + c4);
        }
        cp_commit(); cp_wait<0>();
    }
    __syncthreads();

    // Q fragments (row-block of this warp), kept in regs for all j
    uint32_t qf[8][4];
    {
        const float* Qb = Ps + (w * 16 + qr) * QSTR;
#pragma unroll
        for (int ks = 0; ks < 8; ks++) {
            qf[ks][0] = __float_as_uint(Qb[ks * 8 + qc]);
            qf[ks][1] = __float_as_uint(Qb[8 * QSTR + ks * 8 + qc]);
            qf[ks][2] = __float_as_uint(Qb[ks * 8 + qc + 4]);
            qf[ks][3] = __float_as_uint(Qb[8 * QSTR + ks * 8 + qc + 4]);
        }
    }

    float m0 = -1e30f, m1 = -1e30f, l0 = 0.f, l1 = 0.f;
    float o[8][4];
#pragma unroll
    for (int i = 0; i < 8; i++)
#pragma unroll
        for (int v = 0; v < 4; v++) o[i][v] = 0.f;

    const uint32_t sK = (uint32_t)__cvta_generic_to_shared(Ks);
    const uint32_t sV = (uint32_t)__cvta_generic_to_shared(Vs);
    const int row0 = ib * FBR + w * 16 + qr;
    const int jmax = 2 * ib + 2;

    for (int j = 0; j < jmax; j++) {
        __syncthreads();   // previous iter's K/V reads complete
        for (int e = tid; e < FBC * 16; e += 256) {
            int r = e >> 4, c4 = (e & 15) << 2;
            cp16(sK + (uint32_t)(r * KSTR + c4) * 4u,
                 kbase + (long long)(j * FBC + r) * 3072 + c4);
        }
        for (int e = tid; e < FBC * 16; e += 256) {
            int r = e >> 4, c4 = (e & 15) << 2;
            cp16(sV + (uint32_t)(r * VSTR + c4) * 4u,
                 vbase + (long long)(j * FBC + r) * 3072 + c4);
        }
        cp_commit(); cp_wait<0>();
        __syncthreads();

        // S = Q . K^T
        float s[8][4];
#pragma unroll
        for (int nt = 0; nt < 8; nt++)
#pragma unroll
            for (int v = 0; v < 4; v++) s[nt][v] = 0.f;
#pragma unroll
        for (int ks = 0; ks < 8; ks++) {
            uint32_t bf[8][2];
#pragma unroll
            for (int nt = 0; nt < 8; nt++) {
                const float* Kr = Ks + (nt * 8 + qr) * KSTR + ks * 8 + qc;
                bf[nt][0] = __float_as_uint(Kr[0]);
                bf[nt][1] = __float_as_uint(Kr[4]);
            }
#pragma unroll
            for (int nt = 0; nt < 8; nt++)
                mma8(s[nt], qf[ks], bf[nt]);
        }

        // scale + causal mask
#pragma unroll
        for (int nt = 0; nt < 8; nt++) {
            int c0 = j * FBC + nt * 8 + 2 * qc;
#pragma unroll
            for (int v = 0; v < 4; v++) {
                int cg = c0 + (v & 1);
                int rg = row0 + (v >> 1) * 8;
                float val = s[nt][v] * SCALE;
                s[nt][v] = (cg <= rg) ? val : -1e30f;
            }
        }

        // online softmax
        float rm0 = -1e30f, rm1 = -1e30f;
#pragma unroll
        for (int nt = 0; nt < 8; nt++) {
            rm0 = fmaxf(rm0, fmaxf(s[nt][0], s[nt][1]));
            rm1 = fmaxf(rm1, fmaxf(s[nt][2], s[nt][3]));
        }
        rm0 = fmaxf(rm0, __shfl_xor_sync(0xffffffffu, rm0, 1));
        rm0 = fmaxf(rm0, __shfl_xor_sync(0xffffffffu, rm0, 2));
        rm1 = fmaxf(rm1, __shfl_xor_sync(0xffffffffu, rm1, 1));
        rm1 = fmaxf(rm1, __shfl_xor_sync(0xffffffffu, rm1, 2));
        float nm0 = fmaxf(m0, rm0), nm1 = fmaxf(m1, rm1);
        float a0 = __expf(m0 - nm0), a1 = __expf(m1 - nm1);

        float* Pr = Ps + (w * 16 + qr) * PSTR;
        float sum0 = 0.f, sum1 = 0.f;
#pragma unroll
        for (int nt = 0; nt < 8; nt++) {
            float p0 = __expf(s[nt][0] - nm0);
            float p1 = __expf(s[nt][1] - nm0);
            float p2 = __expf(s[nt][2] - nm1);
            float p3 = __expf(s[nt][3] - nm1);
            sum0 += p0 + p1; sum1 += p2 + p3;
            int c = nt * 8 + 2 * qc;
            Pr[c]     = rnd_tf32(p0);
            Pr[c + 1] = rnd_tf32(p1);
            Pr[8 * PSTR + c]     = rnd_tf32(p2);
            Pr[8 * PSTR + c + 1] = rnd_tf32(p3);
        }
        sum0 += __shfl_xor_sync(0xffffffffu, sum0, 1);
        sum0 += __shfl_xor_sync(0xffffffffu, sum0, 2);
        sum1 += __shfl_xor_sync(0xffffffffu, sum1, 1);
        sum1 += __shfl_xor_sync(0xffffffffu, sum1, 2);
        l0 = l0 * a0 + sum0;
        l1 = l1 * a1 + sum1;
        m0 = nm0; m1 = nm1;
#pragma unroll
        for (int nto = 0; nto < 8; nto++) {
            o[nto][0] *= a0; o[nto][1] *= a0;
            o[nto][2] *= a1; o[nto][3] *= a1;
        }
        __syncwarp();   // P visible within warp

        // O += P . V
#pragma unroll
        for (int ks = 0; ks < 8; ks++) {
            uint32_t pf[4];
            pf[0] = __float_as_uint(Pr[ks * 8 + qc]);
            pf[1] = __float_as_uint(Pr[8 * PSTR + ks * 8 + qc]);
            pf[2] = __float_as_uint(Pr[ks * 8 + qc + 4]);
            pf[3] = __float_as_uint(Pr[8 * PSTR + ks * 8 + qc + 4]);
#pragma unroll
            for (int nto = 0; nto < 8; nto++) {
                uint32_t bf2[2];
                bf2[0] = __float_as_uint(Vs[(ks * 8 + qc) * VSTR + nto * 8 + qr]);
                bf2[1] = __float_as_uint(Vs[(ks * 8 + qc + 4) * VSTR + nto * 8 + qr]);
                mma8(o[nto], pf, bf2);
            }
        }
        __syncwarp();   // P reads done before next iter's P writes
    }

    // normalize + store (rounded tf32, feeds proj GEMM)
    float i0 = 1.f / l0, i1 = 1.f / l1;
    float* arow0 = att + (long long)(b * Tn + row0) * En + h * 64;
    float* arow1 = arow0 + 8ll * En;
#pragma unroll
    for (int nto = 0; nto < 8; nto++) {
        int c = nto * 8 + 2 * qc;
        float2 v0 = { rnd_tf32(o[nto][0] * i0), rnd_tf32(o[nto][1] * i0) };
        float2 v1 = { rnd_tf32(o[nto][2] * i1), rnd_tf32(o[nto][3] * i1) };
        *(float2*)(arow0 + c) = v0;
        *(float2*)(arow1 + c) = v1;
    }
}

// ---------------- weight prep ----------------
__global__ void round_copy(const float* __restrict__ src, float* __restrict__ dst, long long n4)
{
    long long i = (long long)blockIdx.x * blockDim.x + threadIdx.x;
    if (i >= n4) return;
    float4 v = ((const float4*)src)[i];
    v.x = rnd_tf32(v.x); v.y = rnd_tf32(v.y); v.z = rnd_tf32(v.z); v.w = rnd_tf32(v.w);
    ((float4*)dst)[i] = v;
}

// wq/wk/wv [L][H][E][D] -> g_wqkv [L][E][ s*1024 + h*64 + d ]
__global__ void repack_qkv(const float* __restrict__ wq,
                           const float* __restrict__ wk,
                           const float* __restrict__ wv,
                           float* __restrict__ dst)
{
    int le = blockIdx.x;            // l*1024 + e
    int l = le >> 10, e = le & 1023;
    const float* srcs[3] = { wq, wk, wv };
    float* drow = dst + (long long)le * 3072;
    for (int s = 0; s < 3; s++) {
        const float* ws = srcs[s];
        for (int idx = threadIdx.x; idx < 1024; idx += 256) {
            int h = idx >> 6, d = idx & 63;
            float v = ws[(((long long)l * Hn + h) * En + e) * Dn + d];
            drow[s * 1024 + idx] = rnd_tf32(v);
        }
    }
}

__global__ void pad_lm_w(const float* __restrict__ src, float* __restrict__ dst)
{
    int r = blockIdx.x;
    const float* s = src + (long long)r * Vn;
    float* d = dst + (long long)r * VPAD;
    for (int c = threadIdx.x; c < VPAD; c += blockDim.x)
        d[c] = (c < Vn) ? rnd_tf32(s[c]) : 0.f;
}

// ---------------- elementwise ----------------
__global__ void embed_kernel(const int* __restrict__ idx,
                             const float* __restrict__ tok,
                             const float* __restrict__ pos,
                             float* __restrict__ x)
{
    int bt = blockIdx.x;
    int t = bt % Tn;
    int token = idx[bt];
    const float4* tr = (const float4*)(tok + (long long)token * En);
    const float4* pr = (const float4*)(pos + (long long)t * En);
    float4* xr = (float4*)(x + (long long)bt * En);
    int e = threadIdx.x;
    float4 a = tr[e], b = pr[e];
    xr[e] = make_float4(a.x + b.x, a.y + b.y, a.z + b.z, a.w + b.w);
}

// LN over E=1024, 256 threads, one float4/thread; output rounded to tf32
__global__ void ln_kernel(const float* __restrict__ x,
                          const float* __restrict__ g,
                          const float* __restrict__ b,
                          float* __restrict__ out)
{
    int row = blockIdx.x;
    int tid = threadIdx.x, lane = tid & 31, w = tid >> 5;
    const float4* xr = (const float4*)(x + (long long)row * En);
    float4 v = xr[tid];
    __shared__ float red[8];

    float s = v.x + v.y + v.z + v.w;
#pragma unroll
    for (int o = 16; o > 0; o >>= 1) s += __shfl_xor_sync(0xffffffffu, s, o);
    if (lane == 0) red[w] = s;
    __syncthreads();
    float mu = (red[0]+red[1]+red[2]+red[3]+red[4]+red[5]+red[6]+red[7]) * (1.f / En);

    float dx = v.x - mu, dy = v.y - mu, dz = v.z - mu, dw = v.w - mu;
    float vv = dx*dx + dy*dy + dz*dz + dw*dw;
#pragma unroll
    for (int o = 16; o > 0; o >>= 1) vv += __shfl_xor_sync(0xffffffffu, vv, o);
    __syncthreads();
    if (lane == 0) red[w] = vv;
    __syncthreads();
    float rstd = rsqrtf((red[0]+red[1]+red[2]+red[3]+red[4]+red[5]+red[6]+red[7]) * (1.f / En) + EPS);

    const float4 gg = ((const float4*)g)[tid];
    const float4 bb = ((const float4*)b)[tid];
    float4 o4;
    o4.x = rnd_tf32(dx * rstd * gg.x + bb.x);
    o4.y = rnd_tf32(dy * rstd * gg.y + bb.y);
    o4.z = rnd_tf32(dz * rstd * gg.z + bb.z);
    o4.w = rnd_tf32(dw * rstd * gg.w + bb.w);
    ((float4*)(out + (long long)row * En))[tid] = o4;
}

// single-pass online logsumexp NLL
__global__ void nll_kernel(const float* __restrict__ logits,
                           const int* __restrict__ targets,
                           float* __restrict__ rownll)
{
    int row = blockIdx.x;
    const float* lr = logits + (long long)row * Vn;
    int tid = threadIdx.x;
    float m = -1e30f, s = 0.f;
    for (int i = tid; i < Vn; i += 256) {
        float v = lr[i];
        if (v > m) { s = s * __expf(m - v) + 1.f; m = v; }
        else       { s += __expf(v - m); }
    }
    __shared__ float sm[256], ss[256];
    sm[tid] = m; ss[tid] = s;
    __syncthreads();
    for (int o = 128; o > 0; o >>= 1) {
        if (tid < o) {
            float m2 = sm[tid + o], s2 = ss[tid + o];
            float M = fmaxf(sm[tid], m2);
            ss[tid] = ss[tid] * __expf(sm[tid] - M) + s2 * __expf(m2 - M);
            sm[tid] = M;
        }
        __syncthreads();
    }
    if (tid == 0) {
        float lse = sm[0] + logf(ss[0]);
        rownll[row] = -(lr[targets[row]] - lse);
    }
}

__global__ void mean_kernel(const float* __restrict__ rownll, float* __restrict__ out)
{
    __shared__ float red[256];
    int tid = threadIdx.x;
    float s = 0.f;
    for (int i = tid; i < BT; i += 256) s += rownll[i];
    red[tid] = s; __syncthreads();
    for (int o = 128; o > 0; o >>= 1) { if (tid < o) red[tid] += red[tid + o]; __syncthreads(); }
    if (tid == 0) out[0] = red[0] / (float)BT;
}

// ---------------- host launcher ----------------
static constexpr int SMEM_A = 2 * (128 * 36 + 32 * 136) * 4;   // 71680

extern "C" void kernel_launch(void* const* d_in, const int* in_sizes, int n_in,
                              void* d_out, int out_size)
{
    const int*   idx     = (const int*)  d_in[0];
    const int*   targets = (const int*)  d_in[1];
    const float* tok_emb = (const float*)d_in[2];
    const float* pos_emb = (const float*)d_in[3];
    const float* wq      = (const float*)d_in[4];
    const float* wk      = (const float*)d_in[5];
    const float* wv      = (const float*)d_in[6];
    const float* w_proj  = (const float*)d_in[7];
    const float* b_proj  = (const float*)d_in[8];
    const float* ln1_g   = (const float*)d_in[9];
    const float* ln1_b   = (const float*)d_in[10];
    const float* ln2_g   = (const float*)d_in[11];
    const float* ln2_b   = (const float*)d_in[12];
    const float* ff_w1   = (const float*)d_in[13];
    const float* ff_b1   = (const float*)d_in[14];
    const float* ff_w2   = (const float*)d_in[15];
    const float* ff_b2   = (const float*)d_in[16];
    const float* lnf_g   = (const float*)d_in[17];
    const float* lnf_b   = (const float*)d_in[18];
    const float* lm_w    = (const float*)d_in[19];
    const float* lm_b    = (const float*)d_in[20];
    float* out = (float*)d_out;

    float *x, *h, *qkv, *att, *ff, *wqkv, *wprj, *wff1, *wff2, *wpad, *rownll;
    cudaGetSymbolAddress((void**)&x,      g_x);
    cudaGetSymbolAddress((void**)&h,      g_h);
    cudaGetSymbolAddress((void**)&qkv,    g_qkv);
    cudaGetSymbolAddress((void**)&att,    g_att);
    cudaGetSymbolAddress((void**)&ff,     g_ff);
    cudaGetSymbolAddress((void**)&wqkv,   g_wqkv);
    cudaGetSymbolAddress((void**)&wprj,   g_wprj);
    cudaGetSymbolAddress((void**)&wff1,   g_wff1);
    cudaGetSymbolAddress((void**)&wff2,   g_wff2);
    cudaGetSymbolAddress((void**)&wpad,   g_wpad);
    cudaGetSymbolAddress((void**)&rownll, g_rownll);

    auto kA = gemm_tf32<128, 128, 64, 32, 32>;
    cudaFuncSetAttribute(kA, cudaFuncAttributeMaxDynamicSharedMemorySize, SMEM_A);
    cudaFuncSetAttribute(flash_kernel, cudaFuncAttributeMaxDynamicSharedMemorySize, FLASH_SMEM);

    // ---- weight prep (every launch; deterministic, graph-safe) ----
    repack_qkv<<<Ln * En, 256>>>(wq, wk, wv, wqkv);
    {
        long long n4;
        n4 = (long long)Ln * En * En / 4;
        round_copy<<<(unsigned)((n4 + 255) / 256), 256>>>(w_proj, wprj, n4);
        n4 = (long long)Ln * En * FFn / 4;
        round_copy<<<(unsigned)((n4 + 255) / 256), 256>>>(ff_w1, wff1, n4);
        round_copy<<<(unsigned)((n4 + 255) / 256), 256>>>(ff_w2, wff2, n4);
    }
    pad_lm_w<<<En, 256>>>(lm_w, wpad);

    // x = tok_emb[idx] + pos_emb
    embed_kernel<<<BT, 256>>>(idx, tok_emb, pos_emb, x);

    for (int l = 0; l < Ln; l++) {
        // h = LN1(x)  (rounded tf32)
        ln_kernel<<<BT, 256>>>(x, ln1_g + (long long)l * En, ln1_b + (long long)l * En, h);

        // qkv = h @ Wqkv  [4096 x 3072 x 1024], rounded output
        kA<<<dim3(BT / 128, 3 * En / 128), 256, SMEM_A>>>(
            BT, 3 * En, En,
            h, En,
            wqkv + (long long)l * En * 3 * En, 3 * En,
            qkv, 3 * En,
            nullptr, nullptr, 2);

        // fused causal attention -> att (rounded)
        flash_kernel<<<dim3(8, Bn * Hn), 256, FLASH_SMEM>>>(qkv, att);

        // x = x + att @ w_proj + b_proj
        kA<<<dim3(BT / 128, En / 128), 256, SMEM_A>>>(
            BT, En, En,
            att, En,
            wprj + (long long)l * En * En, En,
            x, En,
            b_proj + (long long)l * En, x, 0);

        // h = LN2(x)
        ln_kernel<<<BT, 256>>>(x, ln2_g + (long long)l * En, ln2_b + (long long)l * En, h);

        // ff = relu(h @ ff_w1 + ff_b1)  (rounded)
        kA<<<dim3(BT / 128, FFn / 128), 256, SMEM_A>>>(
            BT, FFn, En,
            h, En,
            wff1 + (long long)l * En * FFn, FFn,
            ff, FFn,
            ff_b1 + (long long)l * FFn, nullptr, 3);

        // x = x + ff @ ff_w2 + ff_b2
        kA<<<dim3(BT / 128, En / 128), 256, SMEM_A>>>(
            BT, En, FFn,
            ff, FFn,
            wff2 + (long long)l * FFn * En, En,
            x, En,
            ff_b2 + (long long)l * En, x, 0);
    }

    // h = LN_f(x)
    ln_kernel<<<BT, 256>>>(x, lnf_g, lnf_b, h);

    // logits = h @ lm_w + lm_b
    kA<<<dim3(BT / 128, VPAD / 128), 256, SMEM_A>>>(
        BT, Vn, En,
        h, En,
        wpad, VPAD,
        out, Vn,
        lm_b, nullptr, 0);

    // loss
    if ((long long)out_size > (long long)BT * Vn) {
        nll_kernel<<<BT, 256>>>(out, targets, rownll);
        mean_kernel<<<1, 256>>>(rownll, out + (long long)BT * Vn);
    }
}